// round 2
// baseline (speedup 1.0000x reference)
#include <cuda_runtime.h>
#include <cstdint>
#include <cstddef>

#define NB 8
#define NA 750000
#define PRE_NMS 4000
#define POST_NMS 1000
#define MIN_SIZE 0.001f
#define IMG_WF 1000.0f
#define IMG_HF 1000.0f
#define CAND_CAP 8192
#define BC_CAP 16384
#define WPR 64          /* mask words per row (63 used; word 63 never written -> 0) */
#define BBOX_CLIP 4.135166556742356f   /* log(1000/16) */

// ---------------- scratch (static device allocations; zero-initialized) ----
__device__ unsigned           g_hist_c[NB * 1024];
__device__ unsigned           g_hist_f[NB * 1024];
__device__ unsigned           g_zero8[NB];
__device__ unsigned           g_bucket_c[NB];
__device__ unsigned           g_above_c[NB];
__device__ unsigned           g_bucket_f[NB];
__device__ unsigned           g_above_f[NB];
__device__ int                g_cand_cnt[NB];
__device__ int                g_bcnt[NB];
__device__ unsigned long long g_cand[NB * CAND_CAP];
__device__ unsigned long long g_bcand[NB * BC_CAP];
__device__ float              g_score[NB * PRE_NMS];
__device__ int                g_idx[NB * PRE_NMS];
__device__ float4             g_box[NB * PRE_NMS];
__device__ float              g_prob[NB * PRE_NMS];
__device__ unsigned           g_vmask32[NB * 128];
__device__ unsigned long long g_mask[(size_t)NB * PRE_NMS * WPR];  // 16 MB
__device__ int                g_keptlist[NB * POST_NMS];
__device__ unsigned long long g_keepmask[NB * 64];
__device__ int                g_nkeep[NB];

// monotone key: larger float -> larger unsigned
__device__ __forceinline__ unsigned fkey(float f) {
    unsigned u = __float_as_uint(f);
    return u ^ ((u & 0x80000000u) ? 0xFFFFFFFFu : 0x80000000u);
}
__device__ __forceinline__ float unkey(unsigned k) {
    return __uint_as_float((k & 0x80000000u) ? (k ^ 0x80000000u) : ~k);
}

// ---------------- K0: zero small scratch ------------------------------------
__global__ void k_zero() {
    int t = blockIdx.x * blockDim.x + threadIdx.x;
    for (int i = t; i < NB * 1024; i += gridDim.x * blockDim.x) {
        g_hist_c[i] = 0u;
        g_hist_f[i] = 0u;
    }
    if (t < NB) { g_cand_cnt[t] = 0; g_bcnt[t] = 0; g_zero8[t] = 0u; }
}

// ---------------- K1: coarse 10-bit histogram (float4) ----------------------
__global__ void k_hist_c(const float* __restrict__ obj) {
    __shared__ unsigned h[1024];
    for (int t = threadIdx.x; t < 1024; t += blockDim.x) h[t] = 0u;
    __syncthreads();
    int img = blockIdx.y;
    const float4* o = (const float4*)(obj + (size_t)img * NA);
    int stride = gridDim.x * blockDim.x;
    for (int i = blockIdx.x * blockDim.x + threadIdx.x; i < NA / 4; i += stride) {
        float4 v = o[i];
        atomicAdd(&h[fkey(v.x) >> 22], 1u);
        atomicAdd(&h[fkey(v.y) >> 22], 1u);
        atomicAdd(&h[fkey(v.z) >> 22], 1u);
        atomicAdd(&h[fkey(v.w) >> 22], 1u);
    }
    __syncthreads();
    for (int t = threadIdx.x; t < 1024; t += blockDim.x)
        if (h[t]) atomicAdd(&g_hist_c[img * 1024 + t], h[t]);
}

// ---------------- K2/K4: pick boundary bucket from a 1024-bin histogram -----
__global__ void k_select(int fine) {
    const unsigned* hist  = fine ? g_hist_f  : g_hist_c;
    const unsigned* basev = fine ? g_above_c : g_zero8;
    unsigned* out_b  = fine ? g_bucket_f : g_bucket_c;
    unsigned* out_ab = fine ? g_above_f  : g_above_c;
    int img = blockIdx.x, t = threadIdx.x;
    __shared__ unsigned sh[1024];
    sh[t] = hist[img * 1024 + (1023 - t)];   // reversed -> prefix = suffix sum
    __syncthreads();
    for (int off = 1; off < 1024; off <<= 1) {
        unsigned v = (t >= off) ? sh[t - off] : 0u;
        __syncthreads();
        sh[t] += v;
        __syncthreads();
    }
    unsigned base   = basev[img];
    unsigned needed = (unsigned)PRE_NMS - base;
    unsigned suff = sh[t];
    unsigned prev = (t == 0) ? 0u : sh[t - 1];
    if (suff >= needed && prev < needed) {
        out_b[img]  = 1023u - (unsigned)t;
        out_ab[img] = base + prev;
    }
}

// ---------------- K3: fine histogram + candidate compaction (fused) ---------
__global__ void k_hist_f(const float* __restrict__ obj) {
    __shared__ unsigned h[1024];
    for (int t = threadIdx.x; t < 1024; t += blockDim.x) h[t] = 0u;
    __syncthreads();
    int img = blockIdx.y;
    unsigned c = g_bucket_c[img];
    const float4* o = (const float4*)(obj + (size_t)img * NA);
    int stride = gridDim.x * blockDim.x;
    for (int i = blockIdx.x * blockDim.x + threadIdx.x; i < NA / 4; i += stride) {
        float4 v = o[i];
#pragma unroll
        for (int j = 0; j < 4; j++) {
            float f = (j == 0) ? v.x : (j == 1) ? v.y : (j == 2) ? v.z : v.w;
            unsigned key = fkey(f);
            unsigned cb = key >> 22;
            if (cb >= c) {
                unsigned long long e = ((unsigned long long)key << 32) |
                                       (unsigned)(~(unsigned)(4 * i + j));
                if (cb == c) {
                    atomicAdd(&h[(key >> 12) & 1023u], 1u);
                    int p = atomicAdd(&g_bcnt[img], 1);
                    if (p < BC_CAP) g_bcand[img * BC_CAP + p] = e;
                } else {
                    int p = atomicAdd(&g_cand_cnt[img], 1);
                    if (p < CAND_CAP) g_cand[img * CAND_CAP + p] = e;
                }
            }
        }
    }
    __syncthreads();
    for (int t = threadIdx.x; t < 1024; t += blockDim.x)
        if (h[t]) atomicAdd(&g_hist_f[img * 1024 + t], h[t]);
}

// ---------------- K5: filter boundary-bucket side buffer --------------------
__global__ void k_compact2() {
    int img = blockIdx.x;
    unsigned T = (g_bucket_c[img] << 10) | g_bucket_f[img];
    int cnt = g_bcnt[img]; if (cnt > BC_CAP) cnt = BC_CAP;
    for (int i = threadIdx.x; i < cnt; i += blockDim.x) {
        unsigned long long e = g_bcand[img * BC_CAP + i];
        if ((unsigned)(e >> 44) >= T) {
            int p = atomicAdd(&g_cand_cnt[img], 1);
            if (p < CAND_CAP) g_cand[img * CAND_CAP + p] = e;
        }
    }
}

// ---------------- K6: bitonic sort candidates, emit top-4000 ----------------
__global__ void k_sort() {
    extern __shared__ unsigned long long s[];
    int img = blockIdx.x;
    int cnt = g_cand_cnt[img];
    if (cnt > CAND_CAP) cnt = CAND_CAP;
    for (int t = threadIdx.x; t < CAND_CAP; t += blockDim.x)
        s[t] = (t < cnt) ? g_cand[img * CAND_CAP + t] : 0ull;
    __syncthreads();
    for (unsigned k = 2; k <= CAND_CAP; k <<= 1) {
        for (unsigned j = k >> 1; j > 0; j >>= 1) {
            for (unsigned idx = threadIdx.x; idx < CAND_CAP; idx += blockDim.x) {
                unsigned ixj = idx ^ j;
                if (ixj > idx) {
                    unsigned long long a = s[idx], b = s[ixj];
                    bool blk = ((idx & k) == 0u);     // descending overall
                    if (blk ? (a < b) : (a > b)) { s[idx] = b; s[ixj] = a; }
                }
            }
            __syncthreads();
        }
    }
    for (int t = threadIdx.x; t < PRE_NMS; t += blockDim.x) {
        unsigned long long key = s[t];
        g_score[img * PRE_NMS + t] = unkey((unsigned)(key >> 32));
        g_idx[img * PRE_NMS + t]   = (int)(~(unsigned)key);
    }
}

// ---------------- K7: decode + clip + valid(ballot) + sigmoid ---------------
__global__ void k_decode(const float* __restrict__ deltas,
                         const float* __restrict__ anchors) {
    int img = blockIdx.y;
    int t = blockIdx.x * blockDim.x + threadIdx.x;
    bool inr = (t < PRE_NMS);
    int idx = inr ? g_idx[img * PRE_NMS + t] : 0;
    float4 a = ((const float4*)anchors)[idx];
    float4 d = ((const float4*)deltas)[(size_t)img * NA + idx];
    float w = a.z - a.x, h = a.w - a.y;
    float cx = a.x + 0.5f * w, cy = a.y + 0.5f * h;
    float dw = fminf(d.z, BBOX_CLIP), dh = fminf(d.w, BBOX_CLIP);
    float pcx = d.x * w + cx, pcy = d.y * h + cy;
    float pw = expf(dw) * w, ph = expf(dh) * h;
    float x1 = pcx - 0.5f * pw, y1 = pcy - 0.5f * ph;
    float x2 = pcx + 0.5f * pw, y2 = pcy + 0.5f * ph;
    x1 = fminf(fmaxf(x1, 0.f), IMG_WF);
    y1 = fminf(fmaxf(y1, 0.f), IMG_HF);
    x2 = fminf(fmaxf(x2, 0.f), IMG_WF);
    y2 = fminf(fmaxf(y2, 0.f), IMG_HF);
    bool validb = false;
    if (inr) {
        g_box[img * PRE_NMS + t] = make_float4(x1, y1, x2, y2);
        validb = ((x2 - x1) >= MIN_SIZE) && ((y2 - y1) >= MIN_SIZE);
        float sc = g_score[img * PRE_NMS + t];
        g_prob[img * PRE_NMS + t] = 1.f / (1.f + expf(-sc));
    }
    unsigned bb = __ballot_sync(0xffffffffu, validb);
    if ((threadIdx.x & 31) == 0 && inr)
        g_vmask32[img * 128 + (t >> 5)] = bb;
}

// ---------------- K8: IoU suppression bitmask (upper triangle, no FDIV) -----
__device__ __forceinline__ bool iou_sup(const float4& r, float rarea,
                                        const float4& q, float carea) {
    float xx1 = fmaxf(r.x, q.x), yy1 = fmaxf(r.y, q.y);
    float xx2 = fminf(r.z, q.z), yy2 = fminf(r.w, q.w);
    float ww = fmaxf(xx2 - xx1, 0.f), hh = fmaxf(yy2 - yy1, 0.f);
    float inter = ww * hh;
    float uni = rarea + carea - inter;
    float hi = 0.700007f * uni;
    float lo = 0.699993f * uni;
    bool sup;
    if (inter > hi)        sup = true;
    else if (inter < lo)   sup = false;
    else                   // rare ambiguous band: bit-exact reference path
        sup = (inter / fmaxf(uni, 1e-9f)) > 0.7f;
    return sup;
}

__global__ void k_iou() {
    int img = blockIdx.z, rb = blockIdx.y, cb = blockIdx.x;
    if (cb < rb) return;                  // lower-tri words stay 0 (never written)
    __shared__ float4 cbox[64];
    __shared__ float  carea[64];
    int col0 = cb * 64;
    int c = col0 + threadIdx.x;
    float4 q = (c < PRE_NMS) ? g_box[img * PRE_NMS + c] : make_float4(0, 0, 0, 0);
    cbox[threadIdx.x] = q;
    carea[threadIdx.x] = (q.z - q.x) * (q.w - q.y);
    __syncthreads();
    int row = rb * 64 + threadIdx.x;
    if (row >= PRE_NMS) return;
    float4 r = g_box[img * PRE_NMS + row];
    float rarea = (r.z - r.x) * (r.w - r.y);
    unsigned long long m = 0ull;
    if (cb == rb) {
        for (int j = 0; j < 64; j++) {
            int col = col0 + j;
            if (col > row && col < PRE_NMS)
                if (iou_sup(r, rarea, cbox[j], carea[j])) m |= (1ull << j);
        }
    } else {
#pragma unroll 8
        for (int j = 0; j < 64; j++)
            if (iou_sup(r, rarea, cbox[j], carea[j])) m |= (1ull << j);
    }
    g_mask[((size_t)img * PRE_NMS + row) * WPR + cb] = m;
}

// ---------------- K9: greedy NMS, 64-row chunk resolve, 1 warp/image --------
__global__ void k_nms() {
    int img = blockIdx.x, lane = threadIdx.x;
    __shared__ unsigned long long diag_sh[64];
    const unsigned* vm = g_vmask32 + img * 128;
    unsigned long long r0 = ~((unsigned long long)vm[2 * lane] |
                              ((unsigned long long)vm[2 * lane + 1] << 32));
    unsigned long long r1 = ~((unsigned long long)vm[64 + 2 * lane] |
                              ((unsigned long long)vm[65 + 2 * lane] << 32));
    const unsigned long long* M = g_mask + (size_t)img * PRE_NMS * WPR;
    // prefetch diag words of chunk 0
    unsigned long long nd0 = M[(size_t)(2 * lane) * WPR + 0];
    unsigned long long nd1 = M[(size_t)(2 * lane + 1) * WPR + 0];
    int n = 0;
    for (int ch = 0; ch < 63; ch++) {
        diag_sh[2 * lane] = nd0;
        diag_sh[2 * lane + 1] = nd1;
        __syncwarp();
        if (ch < 62) {                    // prefetch next chunk's diag
            int base = (ch + 1) * 64;
            int ra = base + 2 * lane, rb2 = ra + 1;
            nd0 = (ra  < PRE_NMS) ? M[(size_t)ra  * WPR + (ch + 1)] : 0ull;
            nd1 = (rb2 < PRE_NMS) ? M[(size_t)rb2 * WPR + (ch + 1)] : 0ull;
        }
        unsigned long long remw = (ch < 32) ? __shfl_sync(0xffffffffu, r0, ch)
                                            : __shfl_sync(0xffffffffu, r1, ch - 32);
        int nbits = (ch == 62) ? (PRE_NMS - 62 * 64) : 64;
        unsigned long long km = 0ull;
        int cnt = n;
#pragma unroll
        for (int b = 0; b < 64; b++) {
            unsigned long long d = diag_sh[b];
            bool keep = (b < nbits) && (cnt < POST_NMS) &&
                        !((remw >> (unsigned)b) & 1ull);
            if (keep) { remw |= d; km |= (1ull << b); cnt++; }
        }
        if (lane == 0) {
            unsigned long long t = km;
            int pos = n;
            while (t) {
                int b = __ffsll((long long)t) - 1;
                t &= t - 1;
                g_keptlist[img * POST_NMS + pos++] = ch * 64 + b;
            }
            g_keepmask[img * 64 + ch] = km;
        }
        n = cnt;
        if (n >= POST_NMS) break;
        // OR kept rows' full masks into remv, 8-wide batches for MLP
        unsigned long long t = km;
        while (t) {
            int rr[8];
#pragma unroll
            for (int u = 0; u < 8; u++) {
                if (t) { rr[u] = ch * 64 + (__ffsll((long long)t) - 1); t &= t - 1; }
                else    rr[u] = -1;
            }
            unsigned long long pa[8], pb[8];
#pragma unroll
            for (int u = 0; u < 8; u++) {
                if (rr[u] >= 0) {
                    const unsigned long long* rp = M + (size_t)rr[u] * WPR;
                    pa[u] = rp[lane];
                    pb[u] = rp[32 + lane];   // word 63 never written -> 0
                } else { pa[u] = 0ull; pb[u] = 0ull; }
            }
#pragma unroll
            for (int u = 0; u < 8; u++) { r0 |= pa[u]; r1 |= pb[u]; }
        }
        __syncwarp();
    }
    if (lane == 0) g_nkeep[img] = n;
}

// ---------------- K10: assemble output --------------------------------------
// layout: [proposals (8,1000,4) f32][scores (8,1000) f32]
__global__ void k_out(float* __restrict__ out) {
    int img = blockIdx.x, tid = threadIdx.x;
    int n = g_nkeep[img];
    int lim = n < POST_NMS ? n : POST_NMS;
    for (int s = tid; s < lim; s += blockDim.x) {
        int i = g_keptlist[img * POST_NMS + s];
        ((float4*)out)[img * POST_NMS + s] = g_box[img * PRE_NMS + i];
        out[NB * POST_NMS * 4 + img * POST_NMS + s] = g_prob[img * PRE_NMS + i];
    }
    if (n >= POST_NMS) return;
    // fill with non-kept indices ascending, score = -inf (top_k tie rule)
    __shared__ unsigned sh[1024];
    unsigned base = 0;
    for (int chunk = 0; chunk < PRE_NMS; chunk += 1024) {
        int i = chunk + tid;
        unsigned f = 0u;
        if (i < PRE_NMS) {
            unsigned long long kw = g_keepmask[img * 64 + (i >> 6)];
            f = ((kw >> (i & 63)) & 1ull) ? 0u : 1u;
        }
        sh[tid] = f;
        __syncthreads();
        for (int off = 1; off < 1024; off <<= 1) {
            unsigned vv = (tid >= off) ? sh[tid - off] : 0u;
            __syncthreads();
            sh[tid] += vv;
            __syncthreads();
        }
        unsigned excl = sh[tid] - f;
        int slot = n + (int)(base + excl);
        if (f && slot < POST_NMS) {
            ((float4*)out)[img * POST_NMS + slot] = g_box[img * PRE_NMS + i];
            out[NB * POST_NMS * 4 + img * POST_NMS + slot] =
                __int_as_float(0xff800000);  // -inf
        }
        base += sh[1023];
        __syncthreads();
    }
}

// ---------------- host ------------------------------------------------------
extern "C" void kernel_launch(void* const* d_in, const int* in_sizes, int n_in,
                              void* d_out, int out_size) {
    const float* obj     = (const float*)d_in[0];   // (8, 750000)
    const float* deltas  = (const float*)d_in[1];   // (8, 750000, 4)
    const float* anchors = (const float*)d_in[2];   // (750000, 4)
    float* out = (float*)d_out;

    k_zero<<<8, 1024>>>();
    k_hist_c<<<dim3(144, NB), 256>>>(obj);
    k_select<<<NB, 1024>>>(0);
    k_hist_f<<<dim3(144, NB), 256>>>(obj);
    k_select<<<NB, 1024>>>(1);
    k_compact2<<<NB, 256>>>();

    cudaFuncSetAttribute(k_sort, cudaFuncAttributeMaxDynamicSharedMemorySize,
                         CAND_CAP * (int)sizeof(unsigned long long));
    k_sort<<<NB, 1024, CAND_CAP * sizeof(unsigned long long)>>>();

    k_decode<<<dim3((PRE_NMS + 255) / 256, NB), 256>>>(deltas, anchors);
    k_iou<<<dim3(63, 63, NB), 64>>>();
    k_nms<<<NB, 32>>>();
    k_out<<<NB, 1024>>>(out);
}

// round 3
// speedup vs baseline: 1.0996x; 1.0996x over previous
#include <cuda_runtime.h>
#include <cstdint>
#include <cstddef>

#define NB 8
#define NA 750000
#define PRE_NMS 4000
#define POST_NMS 1000
#define MIN_SIZE 0.001f
#define IMG_WF 1000.0f
#define IMG_HF 1000.0f
#define CAND_CAP 8192
#define BC_CAP 24576
#define WPR 64          /* mask words per row (63 used; word 63 never written -> 0) */
#define BBOX_CLIP 4.135166556742356f   /* log(1000/16) */

// ---------------- scratch (static device allocations; zero-initialized) ----
__device__ unsigned           g_hist_c[NB * 1024];
__device__ unsigned           g_hist_f[NB * 1024];
__device__ unsigned           g_zero8[NB];
__device__ unsigned           g_bucket_c[NB];
__device__ unsigned           g_above_c[NB];
__device__ unsigned           g_bucket_f[NB];
__device__ unsigned           g_above_f[NB];
__device__ int                g_cand_cnt[NB];
__device__ int                g_bcnt[NB];
__device__ unsigned long long g_cand[NB * CAND_CAP];
__device__ unsigned long long g_bcand[NB * BC_CAP];
__device__ float              g_score[NB * PRE_NMS];
__device__ int                g_idx[NB * PRE_NMS];
__device__ float4             g_box[NB * PRE_NMS];
__device__ float              g_prob[NB * PRE_NMS];
__device__ unsigned           g_vmask32[NB * 128];
__device__ unsigned long long g_mask[(size_t)NB * PRE_NMS * WPR];  // 16 MB
__device__ int                g_keptlist[NB * POST_NMS];
__device__ unsigned long long g_keepmask[NB * 64];
__device__ int                g_nkeep[NB];

// monotone key: larger float -> larger unsigned
__device__ __forceinline__ unsigned fkey(float f) {
    unsigned u = __float_as_uint(f);
    return u ^ ((u & 0x80000000u) ? 0xFFFFFFFFu : 0x80000000u);
}
__device__ __forceinline__ float unkey(unsigned k) {
    return __uint_as_float((k & 0x80000000u) ? (k ^ 0x80000000u) : ~k);
}

// ---------------- K0: zero small scratch ------------------------------------
__global__ void k_zero() {
    int t = blockIdx.x * blockDim.x + threadIdx.x;
    for (int i = t; i < NB * 1024; i += gridDim.x * blockDim.x) {
        g_hist_c[i] = 0u;
        g_hist_f[i] = 0u;
    }
    if (t < NB) { g_cand_cnt[t] = 0; g_bcnt[t] = 0; g_zero8[t] = 0u; }
}

// ---------------- K1: coarse 10-bit histogram (float4) ----------------------
__global__ void k_hist_c(const float* __restrict__ obj) {
    __shared__ unsigned h[1024];
    for (int t = threadIdx.x; t < 1024; t += blockDim.x) h[t] = 0u;
    __syncthreads();
    int img = blockIdx.y;
    const float4* o = (const float4*)(obj + (size_t)img * NA);
    int stride = gridDim.x * blockDim.x;
    for (int i = blockIdx.x * blockDim.x + threadIdx.x; i < NA / 4; i += stride) {
        float4 v = o[i];
        atomicAdd(&h[fkey(v.x) >> 22], 1u);
        atomicAdd(&h[fkey(v.y) >> 22], 1u);
        atomicAdd(&h[fkey(v.z) >> 22], 1u);
        atomicAdd(&h[fkey(v.w) >> 22], 1u);
    }
    __syncthreads();
    for (int t = threadIdx.x; t < 1024; t += blockDim.x)
        if (h[t]) atomicAdd(&g_hist_c[img * 1024 + t], h[t]);
}

// ---------------- K2/K4: pick boundary bucket from a 1024-bin histogram -----
__global__ void k_select(int fine) {
    const unsigned* hist  = fine ? g_hist_f  : g_hist_c;
    const unsigned* basev = fine ? g_above_c : g_zero8;
    unsigned* out_b  = fine ? g_bucket_f : g_bucket_c;
    unsigned* out_ab = fine ? g_above_f  : g_above_c;
    int img = blockIdx.x, t = threadIdx.x;
    __shared__ unsigned sh[1024];
    sh[t] = hist[img * 1024 + (1023 - t)];   // reversed -> prefix = suffix sum
    __syncthreads();
    for (int off = 1; off < 1024; off <<= 1) {
        unsigned v = (t >= off) ? sh[t - off] : 0u;
        __syncthreads();
        sh[t] += v;
        __syncthreads();
    }
    unsigned base   = basev[img];
    unsigned needed = (unsigned)PRE_NMS - base;
    unsigned suff = sh[t];
    unsigned prev = (t == 0) ? 0u : sh[t - 1];
    if (suff >= needed && prev < needed) {
        out_b[img]  = 1023u - (unsigned)t;
        out_ab[img] = base + prev;
    }
}

// ---------------- K3: fine histogram + compaction (warp-aggregated) ---------
__global__ void k_hist_f(const float* __restrict__ obj) {
    __shared__ unsigned h[1024];
    for (int t = threadIdx.x; t < 1024; t += blockDim.x) h[t] = 0u;
    __syncthreads();
    int img = blockIdx.y;
    int lane = threadIdx.x & 31;
    unsigned c = g_bucket_c[img];
    const float4* o = (const float4*)(obj + (size_t)img * NA);
    int stride = gridDim.x * blockDim.x;
    int tid0 = blockIdx.x * blockDim.x + threadIdx.x;
    int nIter = (NA / 4 + stride - 1) / stride;          // warp-uniform
    for (int it = 0; it < nIter; it++) {
        int i = tid0 + it * stride;
        bool inb = (i < NA / 4);
        float4 v = inb ? o[i] : make_float4(-1e30f, -1e30f, -1e30f, -1e30f);
#pragma unroll
        for (int j = 0; j < 4; j++) {
            float f = (j == 0) ? v.x : (j == 1) ? v.y : (j == 2) ? v.z : v.w;
            unsigned key = fkey(f);
            unsigned cb = key >> 22;
            bool isU = inb && (cb > c);
            bool isB = inb && (cb == c);
            unsigned long long e = ((unsigned long long)key << 32) |
                                   (unsigned)(~(unsigned)(4 * i + j));
            if (isB) atomicAdd(&h[(key >> 12) & 1023u], 1u);
            unsigned mu = __ballot_sync(0xffffffffu, isU);
            if (mu) {
                int ldr = __ffs(mu) - 1;
                int base = 0;
                if (lane == ldr) base = atomicAdd(&g_cand_cnt[img], __popc(mu));
                base = __shfl_sync(0xffffffffu, base, ldr);
                if (isU) {
                    int p = base + __popc(mu & ((1u << lane) - 1u));
                    if (p < CAND_CAP) g_cand[img * CAND_CAP + p] = e;
                }
            }
            unsigned mb = __ballot_sync(0xffffffffu, isB);
            if (mb) {
                int ldr = __ffs(mb) - 1;
                int base = 0;
                if (lane == ldr) base = atomicAdd(&g_bcnt[img], __popc(mb));
                base = __shfl_sync(0xffffffffu, base, ldr);
                if (isB) {
                    int p = base + __popc(mb & ((1u << lane) - 1u));
                    if (p < BC_CAP) g_bcand[img * BC_CAP + p] = e;
                }
            }
        }
    }
    __syncthreads();
    for (int t = threadIdx.x; t < 1024; t += blockDim.x)
        if (h[t]) atomicAdd(&g_hist_f[img * 1024 + t], h[t]);
}

// ---------------- K5: filter boundary-bucket side buffer --------------------
__global__ void k_compact2() {
    int img = blockIdx.x;
    int lane = threadIdx.x & 31;
    unsigned T = (g_bucket_c[img] << 10) | g_bucket_f[img];
    int cnt = g_bcnt[img]; if (cnt > BC_CAP) cnt = BC_CAP;
    int nIter = (cnt + blockDim.x - 1) / blockDim.x;
    for (int it = 0; it < nIter; it++) {
        int i = it * blockDim.x + threadIdx.x;
        bool take = false;
        unsigned long long e = 0ull;
        if (i < cnt) {
            e = g_bcand[img * BC_CAP + i];
            take = ((unsigned)(e >> 44) >= T);
        }
        unsigned m = __ballot_sync(0xffffffffu, take);
        if (m) {
            int ldr = __ffs(m) - 1;
            int base = 0;
            if (lane == ldr) base = atomicAdd(&g_cand_cnt[img], __popc(m));
            base = __shfl_sync(0xffffffffu, base, ldr);
            if (take) {
                int p = base + __popc(m & ((1u << lane) - 1u));
                if (p < CAND_CAP) g_cand[img * CAND_CAP + p] = e;
            }
        }
    }
}

// ---------------- K6: bitonic sort candidates (dynamic size), top-4000 ------
__global__ void k_sort() {
    extern __shared__ unsigned long long s[];
    int img = blockIdx.x;
    int cnt = g_cand_cnt[img];
    if (cnt > CAND_CAP) cnt = CAND_CAP;
    unsigned S = (cnt <= 4096) ? 4096u : (unsigned)CAND_CAP;
    for (unsigned t = threadIdx.x; t < S; t += blockDim.x)
        s[t] = (t < (unsigned)cnt) ? g_cand[img * CAND_CAP + t] : 0ull;
    __syncthreads();
    for (unsigned k = 2; k <= S; k <<= 1) {
        for (unsigned j = k >> 1; j > 0; j >>= 1) {
            for (unsigned idx = threadIdx.x; idx < S; idx += blockDim.x) {
                unsigned ixj = idx ^ j;
                if (ixj > idx) {
                    unsigned long long a = s[idx], b = s[ixj];
                    bool blk = ((idx & k) == 0u);     // descending overall
                    if (blk ? (a < b) : (a > b)) { s[idx] = b; s[ixj] = a; }
                }
            }
            __syncthreads();
        }
    }
    for (int t = threadIdx.x; t < PRE_NMS; t += blockDim.x) {
        unsigned long long key = s[t];
        g_score[img * PRE_NMS + t] = unkey((unsigned)(key >> 32));
        g_idx[img * PRE_NMS + t]   = (int)(~(unsigned)key);
    }
}

// ---------------- K7: decode + clip + valid(ballot) + sigmoid ---------------
__global__ void k_decode(const float* __restrict__ deltas,
                         const float* __restrict__ anchors) {
    int img = blockIdx.y;
    int t = blockIdx.x * blockDim.x + threadIdx.x;
    bool inr = (t < PRE_NMS);
    int idx = inr ? g_idx[img * PRE_NMS + t] : 0;
    float4 a = ((const float4*)anchors)[idx];
    float4 d = ((const float4*)deltas)[(size_t)img * NA + idx];
    float w = a.z - a.x, h = a.w - a.y;
    float cx = a.x + 0.5f * w, cy = a.y + 0.5f * h;
    float dw = fminf(d.z, BBOX_CLIP), dh = fminf(d.w, BBOX_CLIP);
    float pcx = d.x * w + cx, pcy = d.y * h + cy;
    float pw = expf(dw) * w, ph = expf(dh) * h;
    float x1 = pcx - 0.5f * pw, y1 = pcy - 0.5f * ph;
    float x2 = pcx + 0.5f * pw, y2 = pcy + 0.5f * ph;
    x1 = fminf(fmaxf(x1, 0.f), IMG_WF);
    y1 = fminf(fmaxf(y1, 0.f), IMG_HF);
    x2 = fminf(fmaxf(x2, 0.f), IMG_WF);
    y2 = fminf(fmaxf(y2, 0.f), IMG_HF);
    bool validb = false;
    if (inr) {
        g_box[img * PRE_NMS + t] = make_float4(x1, y1, x2, y2);
        validb = ((x2 - x1) >= MIN_SIZE) && ((y2 - y1) >= MIN_SIZE);
        float sc = g_score[img * PRE_NMS + t];
        g_prob[img * PRE_NMS + t] = 1.f / (1.f + expf(-sc));
    }
    unsigned bb = __ballot_sync(0xffffffffu, validb);
    if ((threadIdx.x & 31) == 0 && inr)
        g_vmask32[img * 128 + (t >> 5)] = bb;
}

// ---------------- K8: IoU suppression bitmask (branchless, deferred band) ---
__global__ void k_iou() {
    int img = blockIdx.z, rb = blockIdx.y, cb = blockIdx.x;
    if (cb < rb) return;                  // lower-tri words stay 0 (never written)
    __shared__ float4 cbox[64];
    __shared__ float  car[64];
    int col0 = cb * 64;
    int c = col0 + threadIdx.x;
    float4 q = (c < PRE_NMS) ? g_box[img * PRE_NMS + c] : make_float4(0, 0, 0, 0);
    cbox[threadIdx.x] = q;
    car[threadIdx.x] = (q.z - q.x) * (q.w - q.y);
    __syncthreads();
    int row = rb * 64 + threadIdx.x;
    if (row >= PRE_NMS) return;
    float4 r = g_box[img * PRE_NMS + row];
    float ra = (r.z - r.x) * (r.w - r.y);
    unsigned long long msup = 0ull, mband = 0ull;
#pragma unroll 16
    for (int j = 0; j < 64; j++) {
        float4 b = cbox[j];
        float xx1 = fmaxf(r.x, b.x), yy1 = fmaxf(r.y, b.y);
        float xx2 = fminf(r.z, b.z), yy2 = fminf(r.w, b.w);
        float ww = fmaxf(xx2 - xx1, 0.f), hh = fmaxf(yy2 - yy1, 0.f);
        float inter = ww * hh;
        float uni = ra + car[j] - inter;
        bool sup  = inter > 0.700007f * uni;
        bool band = (inter >= 0.699993f * uni) && !sup;
        msup  |= (unsigned long long)sup  << j;
        mband |= (unsigned long long)band << j;
    }
    if (cb == rb) {                       // keep only cols strictly above diagonal
        int rel = row - col0;             // 0..63
        unsigned long long hi = (rel == 63) ? 0ull : (~0ull << (rel + 1));
        msup &= hi;
        mband &= hi;
    }
    while (mband) {                       // rare: bit-exact reference decision
        int j = __ffsll((long long)mband) - 1;
        mband &= mband - 1;
        float4 b = cbox[j];
        float xx1 = fmaxf(r.x, b.x), yy1 = fmaxf(r.y, b.y);
        float xx2 = fminf(r.z, b.z), yy2 = fminf(r.w, b.w);
        float ww = fmaxf(xx2 - xx1, 0.f), hh = fmaxf(yy2 - yy1, 0.f);
        float inter = ww * hh;
        float uni = ra + car[j] - inter;
        if ((inter / fmaxf(uni, 1e-9f)) > 0.7f) msup |= (1ull << j);
    }
    g_mask[((size_t)img * PRE_NMS + row) * WPR + cb] = msup;
}

// ---------------- K9: greedy NMS, 64-row chunk resolve, 1 warp/image --------
__global__ void k_nms() {
    int img = blockIdx.x, lane = threadIdx.x;
    __shared__ unsigned long long diag_sh[64];
    const unsigned* vm = g_vmask32 + img * 128;
    unsigned long long r0 = ~((unsigned long long)vm[2 * lane] |
                              ((unsigned long long)vm[2 * lane + 1] << 32));
    unsigned long long r1 = ~((unsigned long long)vm[64 + 2 * lane] |
                              ((unsigned long long)vm[65 + 2 * lane] << 32));
    const unsigned long long* M = g_mask + (size_t)img * PRE_NMS * WPR;
    // prefetch diag words of chunk 0
    unsigned long long nd0 = M[(size_t)(2 * lane) * WPR + 0];
    unsigned long long nd1 = M[(size_t)(2 * lane + 1) * WPR + 0];
    int n = 0;
    for (int ch = 0; ch < 63; ch++) {
        diag_sh[2 * lane] = nd0;
        diag_sh[2 * lane + 1] = nd1;
        __syncwarp();
        if (ch < 62) {                    // prefetch next chunk's diag
            int base = (ch + 1) * 64;
            int ra = base + 2 * lane, rb2 = ra + 1;
            nd0 = (ra  < PRE_NMS) ? M[(size_t)ra  * WPR + (ch + 1)] : 0ull;
            nd1 = (rb2 < PRE_NMS) ? M[(size_t)rb2 * WPR + (ch + 1)] : 0ull;
        }
        unsigned long long remw = (ch < 32) ? __shfl_sync(0xffffffffu, r0, ch)
                                            : __shfl_sync(0xffffffffu, r1, ch - 32);
        int nbits = (ch == 62) ? (PRE_NMS - 62 * 64) : 64;
        unsigned long long km = 0ull;
        int cnt = n;
#pragma unroll
        for (int b = 0; b < 64; b++) {
            unsigned long long d = diag_sh[b];
            bool keep = (b < nbits) && (cnt < POST_NMS) &&
                        !((remw >> (unsigned)b) & 1ull);
            if (keep) { remw |= d; km |= (1ull << b); cnt++; }
        }
        if (lane == 0) {
            unsigned long long t = km;
            int pos = n;
            while (t) {
                int b = __ffsll((long long)t) - 1;
                t &= t - 1;
                g_keptlist[img * POST_NMS + pos++] = ch * 64 + b;
            }
            g_keepmask[img * 64 + ch] = km;
        }
        n = cnt;
        if (n >= POST_NMS) break;
        // OR kept rows' full masks into remv, 8-wide batches for MLP
        unsigned long long t = km;
        while (t) {
            int rr[8];
#pragma unroll
            for (int u = 0; u < 8; u++) {
                if (t) { rr[u] = ch * 64 + (__ffsll((long long)t) - 1); t &= t - 1; }
                else    rr[u] = -1;
            }
            unsigned long long pa[8], pb[8];
#pragma unroll
            for (int u = 0; u < 8; u++) {
                if (rr[u] >= 0) {
                    const unsigned long long* rp = M + (size_t)rr[u] * WPR;
                    pa[u] = rp[lane];
                    pb[u] = rp[32 + lane];   // word 63 never written -> 0
                } else { pa[u] = 0ull; pb[u] = 0ull; }
            }
#pragma unroll
            for (int u = 0; u < 8; u++) { r0 |= pa[u]; r1 |= pb[u]; }
        }
        __syncwarp();
    }
    if (lane == 0) g_nkeep[img] = n;
}

// ---------------- K10: assemble output --------------------------------------
// layout: [proposals (8,1000,4) f32][scores (8,1000) f32]
__global__ void k_out(float* __restrict__ out) {
    int img = blockIdx.x, tid = threadIdx.x;
    int n = g_nkeep[img];
    int lim = n < POST_NMS ? n : POST_NMS;
    for (int s = tid; s < lim; s += blockDim.x) {
        int i = g_keptlist[img * POST_NMS + s];
        ((float4*)out)[img * POST_NMS + s] = g_box[img * PRE_NMS + i];
        out[NB * POST_NMS * 4 + img * POST_NMS + s] = g_prob[img * PRE_NMS + i];
    }
    if (n >= POST_NMS) return;
    // fill with non-kept indices ascending, score = -inf (top_k tie rule)
    __shared__ unsigned sh[1024];
    unsigned base = 0;
    for (int chunk = 0; chunk < PRE_NMS; chunk += 1024) {
        int i = chunk + tid;
        unsigned f = 0u;
        if (i < PRE_NMS) {
            unsigned long long kw = g_keepmask[img * 64 + (i >> 6)];
            f = ((kw >> (i & 63)) & 1ull) ? 0u : 1u;
        }
        sh[tid] = f;
        __syncthreads();
        for (int off = 1; off < 1024; off <<= 1) {
            unsigned vv = (tid >= off) ? sh[tid - off] : 0u;
            __syncthreads();
            sh[tid] += vv;
            __syncthreads();
        }
        unsigned excl = sh[tid] - f;
        int slot = n + (int)(base + excl);
        if (f && slot < POST_NMS) {
            ((float4*)out)[img * POST_NMS + slot] = g_box[img * PRE_NMS + i];
            out[NB * POST_NMS * 4 + img * POST_NMS + slot] =
                __int_as_float(0xff800000);  // -inf
        }
        base += sh[1023];
        __syncthreads();
    }
}

// ---------------- host ------------------------------------------------------
extern "C" void kernel_launch(void* const* d_in, const int* in_sizes, int n_in,
                              void* d_out, int out_size) {
    const float* obj     = (const float*)d_in[0];   // (8, 750000)
    const float* deltas  = (const float*)d_in[1];   // (8, 750000, 4)
    const float* anchors = (const float*)d_in[2];   // (750000, 4)
    float* out = (float*)d_out;

    k_zero<<<8, 1024>>>();
    k_hist_c<<<dim3(144, NB), 256>>>(obj);
    k_select<<<NB, 1024>>>(0);
    k_hist_f<<<dim3(144, NB), 256>>>(obj);
    k_select<<<NB, 1024>>>(1);
    k_compact2<<<NB, 256>>>();

    cudaFuncSetAttribute(k_sort, cudaFuncAttributeMaxDynamicSharedMemorySize,
                         CAND_CAP * (int)sizeof(unsigned long long));
    k_sort<<<NB, 1024, CAND_CAP * sizeof(unsigned long long)>>>();

    k_decode<<<dim3((PRE_NMS + 255) / 256, NB), 256>>>(deltas, anchors);
    k_iou<<<dim3(63, 63, NB), 64>>>();
    k_nms<<<NB, 32>>>();
    k_out<<<NB, 1024>>>(out);
}

// round 4
// speedup vs baseline: 1.2802x; 1.1642x over previous
#include <cuda_runtime.h>
#include <cstdint>
#include <cstddef>

#define NB 8
#define NA 750000
#define PRE_NMS 4000
#define POST_NMS 1000
#define MIN_SIZE 0.001f
#define IMG_WF 1000.0f
#define IMG_HF 1000.0f
#define CAND_CAP 8192
#define BC_CAP 24576
#define SBUF 1024
#define WPR 64          /* mask words per row (63 used; word 63 never written -> 0) */
#define BBOX_CLIP 4.135166556742356f   /* log(1000/16) */

// ---------------- scratch (static device allocations; zero-initialized) ----
__device__ unsigned           g_hist_c[NB * 1024];
__device__ unsigned           g_hist_f[NB * 1024];
__device__ unsigned           g_zero8[NB];
__device__ unsigned           g_bucket_c[NB];
__device__ unsigned           g_above_c[NB];
__device__ unsigned           g_bucket_f[NB];
__device__ unsigned           g_above_f[NB];
__device__ int                g_cand_cnt[NB];
__device__ int                g_bcnt[NB];
__device__ unsigned long long g_cand[NB * CAND_CAP];
__device__ unsigned long long g_bcand[NB * BC_CAP];
__device__ float              g_score[NB * PRE_NMS];
__device__ int                g_idx[NB * PRE_NMS];
__device__ float4             g_box[NB * PRE_NMS];
__device__ float              g_prob[NB * PRE_NMS];
__device__ unsigned           g_vmask32[NB * 128];
__device__ unsigned long long g_mask[(size_t)NB * PRE_NMS * WPR];  // 16 MB
__device__ int                g_keptlist[NB * POST_NMS];
__device__ unsigned long long g_keepmask[NB * 64];
__device__ int                g_nkeep[NB];

// monotone key: larger float -> larger unsigned
__device__ __forceinline__ unsigned fkey(float f) {
    unsigned u = __float_as_uint(f);
    return u ^ ((u & 0x80000000u) ? 0xFFFFFFFFu : 0x80000000u);
}
__device__ __forceinline__ float unkey(unsigned k) {
    return __uint_as_float((k & 0x80000000u) ? (k ^ 0x80000000u) : ~k);
}

// ---------------- K0: zero small scratch ------------------------------------
__global__ void k_zero() {
    int t = blockIdx.x * blockDim.x + threadIdx.x;
    for (int i = t; i < NB * 1024; i += gridDim.x * blockDim.x) {
        g_hist_c[i] = 0u;
        g_hist_f[i] = 0u;
    }
    if (t < NB) { g_cand_cnt[t] = 0; g_bcnt[t] = 0; g_zero8[t] = 0u; }
}

// ---------------- K1: coarse 10-bit histogram (float4, 2x unroll) -----------
__global__ void k_hist_c(const float* __restrict__ obj) {
    __shared__ unsigned h[1024];
    for (int t = threadIdx.x; t < 1024; t += blockDim.x) h[t] = 0u;
    __syncthreads();
    int img = blockIdx.y;
    const float4* o = (const float4*)(obj + (size_t)img * NA);
    int stride = gridDim.x * blockDim.x;
    int i = blockIdx.x * blockDim.x + threadIdx.x;
    for (; i + stride < NA / 4; i += 2 * stride) {
        float4 v0 = o[i];
        float4 v1 = o[i + stride];
        atomicAdd(&h[fkey(v0.x) >> 22], 1u);
        atomicAdd(&h[fkey(v0.y) >> 22], 1u);
        atomicAdd(&h[fkey(v0.z) >> 22], 1u);
        atomicAdd(&h[fkey(v0.w) >> 22], 1u);
        atomicAdd(&h[fkey(v1.x) >> 22], 1u);
        atomicAdd(&h[fkey(v1.y) >> 22], 1u);
        atomicAdd(&h[fkey(v1.z) >> 22], 1u);
        atomicAdd(&h[fkey(v1.w) >> 22], 1u);
    }
    if (i < NA / 4) {
        float4 v = o[i];
        atomicAdd(&h[fkey(v.x) >> 22], 1u);
        atomicAdd(&h[fkey(v.y) >> 22], 1u);
        atomicAdd(&h[fkey(v.z) >> 22], 1u);
        atomicAdd(&h[fkey(v.w) >> 22], 1u);
    }
    __syncthreads();
    for (int t = threadIdx.x; t < 1024; t += blockDim.x)
        if (h[t]) atomicAdd(&g_hist_c[img * 1024 + t], h[t]);
}

// ---------------- K2/K4: pick boundary bucket (1 warp/image) ----------------
__global__ void k_select(int fine) {
    const unsigned* hist  = fine ? g_hist_f  : g_hist_c;
    const unsigned* basev = fine ? g_above_c : g_zero8;
    unsigned* out_b  = fine ? g_bucket_f : g_bucket_c;
    unsigned* out_ab = fine ? g_above_f  : g_above_c;
    int img = blockIdx.x, lane = threadIdx.x;
    const unsigned* H = hist + img * 1024;
    unsigned part = 0;
    for (int r = lane * 32; r < lane * 32 + 32; r++) part += H[1023 - r];
    unsigned inc = part;
    for (int off = 1; off < 32; off <<= 1) {
        unsigned v = __shfl_up_sync(0xffffffffu, inc, off);
        if (lane >= off) inc += v;
    }
    unsigned base   = basev[img];
    unsigned needed = (unsigned)PRE_NMS - base;
    unsigned excl = inc - part;
    bool has = (inc >= needed) && (excl < needed);
    if (has) {
        unsigned acc = excl;
        for (int r = lane * 32; r < lane * 32 + 32; r++) {
            unsigned hv = H[1023 - r];
            if (acc + hv >= needed) {
                out_b[img]  = (unsigned)(1023 - r);
                out_ab[img] = base + acc;
                break;
            }
            acc += hv;
        }
    }
}

// ---------------- K3: fine histogram + collect (block-staged) ---------------
__global__ void k_hist_f(const float* __restrict__ obj) {
    __shared__ unsigned h[1024];
    __shared__ unsigned long long su[SBUF], sb[SBUF];
    __shared__ int scu, scb, gu, gb;
    for (int t = threadIdx.x; t < 1024; t += blockDim.x) h[t] = 0u;
    if (threadIdx.x == 0) { scu = 0; scb = 0; }
    __syncthreads();
    int img = blockIdx.y;
    unsigned c = g_bucket_c[img];
    const float4* o = (const float4*)(obj + (size_t)img * NA);
    int stride = gridDim.x * blockDim.x;
    for (int i = blockIdx.x * blockDim.x + threadIdx.x; i < NA / 4; i += stride) {
        float4 v = o[i];
        unsigned k0 = fkey(v.x), k1 = fkey(v.y), k2 = fkey(v.z), k3 = fkey(v.w);
        unsigned mx = max(max(k0, k1), max(k2, k3));
        if ((mx >> 22) < c) continue;          // fast path: ~92% of iterations
#pragma unroll
        for (int j = 0; j < 4; j++) {
            unsigned key = (j == 0) ? k0 : (j == 1) ? k1 : (j == 2) ? k2 : k3;
            unsigned cb = key >> 22;
            if (cb < c) continue;
            unsigned long long e = ((unsigned long long)key << 32) |
                                   (unsigned)(~(unsigned)(4 * i + j));
            if (cb > c) {
                int p = atomicAdd(&scu, 1);
                if (p < SBUF) su[p] = e;
                else {
                    int q = atomicAdd(&g_cand_cnt[img], 1);
                    if (q < CAND_CAP) g_cand[img * CAND_CAP + q] = e;
                }
            } else {
                atomicAdd(&h[(key >> 12) & 1023u], 1u);
                int p = atomicAdd(&scb, 1);
                if (p < SBUF) sb[p] = e;
                else {
                    int q = atomicAdd(&g_bcnt[img], 1);
                    if (q < BC_CAP) g_bcand[img * BC_CAP + q] = e;
                }
            }
        }
    }
    __syncthreads();
    if (threadIdx.x == 0) {
        int a = scu < SBUF ? scu : SBUF;
        gu = atomicAdd(&g_cand_cnt[img], a);
        int b2 = scb < SBUF ? scb : SBUF;
        gb = atomicAdd(&g_bcnt[img], b2);
    }
    __syncthreads();
    int nu = scu < SBUF ? scu : SBUF;
    for (int p = threadIdx.x; p < nu; p += blockDim.x) {
        int q = gu + p;
        if (q < CAND_CAP) g_cand[img * CAND_CAP + q] = su[p];
    }
    int nb = scb < SBUF ? scb : SBUF;
    for (int p = threadIdx.x; p < nb; p += blockDim.x) {
        int q = gb + p;
        if (q < BC_CAP) g_bcand[img * BC_CAP + q] = sb[p];
    }
    for (int t = threadIdx.x; t < 1024; t += blockDim.x)
        if (h[t]) atomicAdd(&g_hist_f[img * 1024 + t], h[t]);
}

// ---------------- K5: filter boundary-bucket side buffer --------------------
__global__ void k_compact2() {
    int img = blockIdx.x;
    int lane = threadIdx.x & 31;
    unsigned T = (g_bucket_c[img] << 10) | g_bucket_f[img];
    int cnt = g_bcnt[img]; if (cnt > BC_CAP) cnt = BC_CAP;
    int nIter = (cnt + blockDim.x - 1) / blockDim.x;
    for (int it = 0; it < nIter; it++) {
        int i = it * blockDim.x + threadIdx.x;
        bool take = false;
        unsigned long long e = 0ull;
        if (i < cnt) {
            e = g_bcand[img * BC_CAP + i];
            take = ((unsigned)(e >> 44) >= T);
        }
        unsigned m = __ballot_sync(0xffffffffu, take);
        if (m) {
            int ldr = __ffs(m) - 1;
            int base = 0;
            if (lane == ldr) base = atomicAdd(&g_cand_cnt[img], __popc(m));
            base = __shfl_sync(0xffffffffu, base, ldr);
            if (take) {
                int p = base + __popc(m & ((1u << lane) - 1u));
                if (p < CAND_CAP) g_cand[img * CAND_CAP + p] = e;
            }
        }
    }
}

// ---------------- K6: bitonic sort candidates (dynamic size), top-4000 ------
__global__ void k_sort() {
    extern __shared__ unsigned long long s[];
    int img = blockIdx.x;
    int cnt = g_cand_cnt[img];
    if (cnt > CAND_CAP) cnt = CAND_CAP;
    unsigned S = (cnt <= 4096) ? 4096u : (unsigned)CAND_CAP;
    for (unsigned t = threadIdx.x; t < S; t += blockDim.x)
        s[t] = (t < (unsigned)cnt) ? g_cand[img * CAND_CAP + t] : 0ull;
    __syncthreads();
    for (unsigned k = 2; k <= S; k <<= 1) {
        for (unsigned j = k >> 1; j > 0; j >>= 1) {
            for (unsigned idx = threadIdx.x; idx < S; idx += blockDim.x) {
                unsigned ixj = idx ^ j;
                if (ixj > idx) {
                    unsigned long long a = s[idx], b = s[ixj];
                    bool blk = ((idx & k) == 0u);     // descending overall
                    if (blk ? (a < b) : (a > b)) { s[idx] = b; s[ixj] = a; }
                }
            }
            __syncthreads();
        }
    }
    for (int t = threadIdx.x; t < PRE_NMS; t += blockDim.x) {
        unsigned long long key = s[t];
        g_score[img * PRE_NMS + t] = unkey((unsigned)(key >> 32));
        g_idx[img * PRE_NMS + t]   = (int)(~(unsigned)key);
    }
}

// ---------------- K7: decode + clip + valid(ballot) + sigmoid ---------------
__global__ void k_decode(const float* __restrict__ deltas,
                         const float* __restrict__ anchors) {
    int img = blockIdx.y;
    int t = blockIdx.x * blockDim.x + threadIdx.x;
    bool inr = (t < PRE_NMS);
    int idx = inr ? g_idx[img * PRE_NMS + t] : 0;
    float4 a = ((const float4*)anchors)[idx];
    float4 d = ((const float4*)deltas)[(size_t)img * NA + idx];
    float w = a.z - a.x, h = a.w - a.y;
    float cx = a.x + 0.5f * w, cy = a.y + 0.5f * h;
    float dw = fminf(d.z, BBOX_CLIP), dh = fminf(d.w, BBOX_CLIP);
    float pcx = d.x * w + cx, pcy = d.y * h + cy;
    float pw = expf(dw) * w, ph = expf(dh) * h;
    float x1 = pcx - 0.5f * pw, y1 = pcy - 0.5f * ph;
    float x2 = pcx + 0.5f * pw, y2 = pcy + 0.5f * ph;
    x1 = fminf(fmaxf(x1, 0.f), IMG_WF);
    y1 = fminf(fmaxf(y1, 0.f), IMG_HF);
    x2 = fminf(fmaxf(x2, 0.f), IMG_WF);
    y2 = fminf(fmaxf(y2, 0.f), IMG_HF);
    bool validb = false;
    if (inr) {
        g_box[img * PRE_NMS + t] = make_float4(x1, y1, x2, y2);
        validb = ((x2 - x1) >= MIN_SIZE) && ((y2 - y1) >= MIN_SIZE);
        float sc = g_score[img * PRE_NMS + t];
        g_prob[img * PRE_NMS + t] = 1.f / (1.f + expf(-sc));
    }
    unsigned bb = __ballot_sync(0xffffffffu, validb);
    if ((threadIdx.x & 31) == 0 && inr)
        g_vmask32[img * 128 + (t >> 5)] = bb;
}

// ---------------- K8: IoU suppression bitmask (branchless, deferred band) ---
__global__ void k_iou() {
    int img = blockIdx.z, rb = blockIdx.y, cb = blockIdx.x;
    if (cb < rb) return;                  // lower-tri words stay 0 (never written)
    __shared__ float4 cbox[64];
    __shared__ float  car[64];
    int col0 = cb * 64;
    int c = col0 + threadIdx.x;
    float4 q = (c < PRE_NMS) ? g_box[img * PRE_NMS + c] : make_float4(0, 0, 0, 0);
    cbox[threadIdx.x] = q;
    car[threadIdx.x] = (q.z - q.x) * (q.w - q.y);
    __syncthreads();
    int row = rb * 64 + threadIdx.x;
    if (row >= PRE_NMS) return;
    float4 r = g_box[img * PRE_NMS + row];
    float ra = (r.z - r.x) * (r.w - r.y);
    unsigned long long msup = 0ull, mband = 0ull;
#pragma unroll 16
    for (int j = 0; j < 64; j++) {
        float4 b = cbox[j];
        float xx1 = fmaxf(r.x, b.x), yy1 = fmaxf(r.y, b.y);
        float xx2 = fminf(r.z, b.z), yy2 = fminf(r.w, b.w);
        float ww = fmaxf(xx2 - xx1, 0.f), hh = fmaxf(yy2 - yy1, 0.f);
        float inter = ww * hh;
        float uni = ra + car[j] - inter;
        bool sup  = inter > 0.700007f * uni;
        bool band = (inter >= 0.699993f * uni) && !sup;
        msup  |= (unsigned long long)sup  << j;
        mband |= (unsigned long long)band << j;
    }
    if (cb == rb) {                       // keep only cols strictly above diagonal
        int rel = row - col0;             // 0..63
        unsigned long long hi = (rel == 63) ? 0ull : (~0ull << (rel + 1));
        msup &= hi;
        mband &= hi;
    }
    while (mband) {                       // rare: bit-exact reference decision
        int j = __ffsll((long long)mband) - 1;
        mband &= mband - 1;
        float4 b = cbox[j];
        float xx1 = fmaxf(r.x, b.x), yy1 = fmaxf(r.y, b.y);
        float xx2 = fminf(r.z, b.z), yy2 = fminf(r.w, b.w);
        float ww = fmaxf(xx2 - xx1, 0.f), hh = fmaxf(yy2 - yy1, 0.f);
        float inter = ww * hh;
        float uni = ra + car[j] - inter;
        if ((inter / fmaxf(uni, 1e-9f)) > 0.7f) msup |= (1ull << j);
    }
    g_mask[((size_t)img * PRE_NMS + row) * WPR + cb] = msup;
}

// ---------------- K9: greedy NMS, short-chain resolve, 1 warp/image ---------
// Cap-free resolve: suppression decisions are independent of the 1000 cap
// (cap only selects output). Bits >= 4000 are pre-marked removed via vmask.
__global__ void k_nms() {
    int img = blockIdx.x, lane = threadIdx.x;
    __shared__ unsigned long long diag_sh[64];
    const unsigned* vm = g_vmask32 + img * 128;
    unsigned long long r0 = ~((unsigned long long)vm[2 * lane] |
                              ((unsigned long long)vm[2 * lane + 1] << 32));
    unsigned long long r1 = ~((unsigned long long)vm[64 + 2 * lane] |
                              ((unsigned long long)vm[65 + 2 * lane] << 32));
    const unsigned long long* M = g_mask + (size_t)img * PRE_NMS * WPR;
    unsigned long long nd0 = M[(size_t)(2 * lane) * WPR + 0];
    unsigned long long nd1 = M[(size_t)(2 * lane + 1) * WPR + 0];
    int n = 0;
    for (int ch = 0; ch < 63; ch++) {
        diag_sh[2 * lane] = nd0;
        diag_sh[2 * lane + 1] = nd1;
        __syncwarp();
        if (ch < 62) {                    // prefetch next chunk's diag
            int base = (ch + 1) * 64;
            int ra2 = base + 2 * lane, rb2 = ra2 + 1;
            nd0 = (ra2 < PRE_NMS) ? M[(size_t)ra2 * WPR + (ch + 1)] : 0ull;
            nd1 = (rb2 < PRE_NMS) ? M[(size_t)rb2 * WPR + (ch + 1)] : 0ull;
        }
        unsigned long long remw = (ch < 32) ? __shfl_sync(0xffffffffu, r0, ch)
                                            : __shfl_sync(0xffffffffu, r1, ch - 32);
        unsigned long long km = 0ull;
#pragma unroll
        for (int b = 0; b < 64; b++) {
            unsigned long long d = diag_sh[b];
            bool keep = (remw & (1ull << b)) == 0ull;
            remw |= keep ? d : 0ull;              // pred-as-data SEL path
            km   |= keep ? (1ull << b) : 0ull;    // off critical chain
        }
        if (lane == 0) {
            unsigned long long t = km;
            int pos = n;
            while (t && pos < POST_NMS) {
                int b = __ffsll((long long)t) - 1;
                t &= t - 1;
                g_keptlist[img * POST_NMS + pos++] = ch * 64 + b;
            }
            g_keepmask[img * 64 + ch] = km;
        }
        n += __popcll(km);
        if (n >= POST_NMS) break;
        // OR kept rows' full masks into remv, 16-wide batches for MLP
        unsigned long long t = km;
        while (t) {
            int rr[16];
#pragma unroll
            for (int u = 0; u < 16; u++) {
                if (t) { rr[u] = ch * 64 + (__ffsll((long long)t) - 1); t &= t - 1; }
                else    rr[u] = -1;
            }
            unsigned long long pa[16], pb[16];
#pragma unroll
            for (int u = 0; u < 16; u++) {
                if (rr[u] >= 0) {
                    const unsigned long long* rp = M + (size_t)rr[u] * WPR;
                    pa[u] = rp[lane];
                    pb[u] = rp[32 + lane];   // word 63 never written -> 0
                } else { pa[u] = 0ull; pb[u] = 0ull; }
            }
#pragma unroll
            for (int u = 0; u < 16; u++) { r0 |= pa[u]; r1 |= pb[u]; }
        }
        __syncwarp();
    }
    if (lane == 0) g_nkeep[img] = (n < POST_NMS) ? n : POST_NMS;
}

// ---------------- K10: assemble output --------------------------------------
// layout: [proposals (8,1000,4) f32][scores (8,1000) f32]
__global__ void k_out(float* __restrict__ out) {
    int img = blockIdx.x, tid = threadIdx.x;
    int n = g_nkeep[img];
    int lim = n < POST_NMS ? n : POST_NMS;
    for (int s = tid; s < lim; s += blockDim.x) {
        int i = g_keptlist[img * POST_NMS + s];
        ((float4*)out)[img * POST_NMS + s] = g_box[img * PRE_NMS + i];
        out[NB * POST_NMS * 4 + img * POST_NMS + s] = g_prob[img * PRE_NMS + i];
    }
    if (n >= POST_NMS) return;
    // fill with non-kept indices ascending, score = -inf (top_k tie rule)
    __shared__ unsigned sh[1024];
    unsigned base = 0;
    for (int chunk = 0; chunk < PRE_NMS; chunk += 1024) {
        int i = chunk + tid;
        unsigned f = 0u;
        if (i < PRE_NMS) {
            unsigned long long kw = g_keepmask[img * 64 + (i >> 6)];
            f = ((kw >> (i & 63)) & 1ull) ? 0u : 1u;
        }
        sh[tid] = f;
        __syncthreads();
        for (int off = 1; off < 1024; off <<= 1) {
            unsigned vv = (tid >= off) ? sh[tid - off] : 0u;
            __syncthreads();
            sh[tid] += vv;
            __syncthreads();
        }
        unsigned excl = sh[tid] - f;
        int slot = n + (int)(base + excl);
        if (f && slot < POST_NMS) {
            ((float4*)out)[img * POST_NMS + slot] = g_box[img * PRE_NMS + i];
            out[NB * POST_NMS * 4 + img * POST_NMS + slot] =
                __int_as_float(0xff800000);  // -inf
        }
        base += sh[1023];
        __syncthreads();
    }
}

// ---------------- host ------------------------------------------------------
extern "C" void kernel_launch(void* const* d_in, const int* in_sizes, int n_in,
                              void* d_out, int out_size) {
    const float* obj     = (const float*)d_in[0];   // (8, 750000)
    const float* deltas  = (const float*)d_in[1];   // (8, 750000, 4)
    const float* anchors = (const float*)d_in[2];   // (750000, 4)
    float* out = (float*)d_out;

    k_zero<<<8, 1024>>>();
    k_hist_c<<<dim3(144, NB), 256>>>(obj);
    k_select<<<NB, 32>>>(0);
    k_hist_f<<<dim3(144, NB), 256>>>(obj);
    k_select<<<NB, 32>>>(1);
    k_compact2<<<NB, 256>>>();

    cudaFuncSetAttribute(k_sort, cudaFuncAttributeMaxDynamicSharedMemorySize,
                         CAND_CAP * (int)sizeof(unsigned long long));
    k_sort<<<NB, 1024, CAND_CAP * sizeof(unsigned long long)>>>();

    k_decode<<<dim3((PRE_NMS + 255) / 256, NB), 256>>>(deltas, anchors);
    k_iou<<<dim3(63, 63, NB), 64>>>();
    k_nms<<<NB, 32>>>();
    k_out<<<NB, 1024>>>(out);
}

// round 8
// speedup vs baseline: 1.4097x; 1.1012x over previous
#include <cuda_runtime.h>
#include <cstdint>
#include <cstddef>

#define NB 8
#define NA 750000
#define PRE_NMS 4000
#define POST_NMS 1000
#define MIN_SIZE 0.001f
#define IMG_WF 1000.0f
#define IMG_HF 1000.0f
#define CAND_CAP 8192
#define BC_CAP 24576
#define SBUF 1024
#define WPR 64          /* mask words per row (63 used; word 63 never written -> 0) */
#define BBOX_CLIP 4.135166556742356f   /* log(1000/16) */

typedef unsigned long long u64;

// ---------------- scratch (static device allocations; zero-initialized) ----
__device__ unsigned g_hist_c[NB * 1024];
__device__ unsigned g_hist_f[NB * 1024];
__device__ unsigned g_bucket_c[NB];
__device__ unsigned g_above_c[NB];
__device__ int      g_cand_cnt[NB];
__device__ int      g_bcnt[NB];
__device__ u64      g_cand[NB * CAND_CAP];
__device__ u64      g_bcand[NB * BC_CAP];
__device__ float4   g_box[NB * PRE_NMS];
__device__ float    g_prob[NB * PRE_NMS];
__device__ unsigned g_vmask32[NB * 128];
__device__ u64      g_mask[(size_t)NB * PRE_NMS * WPR];  // 16 MB

// monotone key: larger float -> larger unsigned
__device__ __forceinline__ unsigned fkey(float f) {
    unsigned u = __float_as_uint(f);
    return u ^ ((u & 0x80000000u) ? 0xFFFFFFFFu : 0x80000000u);
}
__device__ __forceinline__ float unkey(unsigned k) {
    return __uint_as_float((k & 0x80000000u) ? (k ^ 0x80000000u) : ~k);
}

// ---------------- K0: zero small scratch ------------------------------------
__global__ void k_zero() {
    int t = blockIdx.x * blockDim.x + threadIdx.x;
    for (int i = t; i < NB * 1024; i += gridDim.x * blockDim.x) {
        g_hist_c[i] = 0u;
        g_hist_f[i] = 0u;
    }
    if (t < NB) { g_cand_cnt[t] = 0; g_bcnt[t] = 0; }
}

// ---------------- K1: coarse 10-bit histogram (float4, 2x unroll) -----------
__global__ void k_hist_c(const float* __restrict__ obj) {
    __shared__ unsigned h[1024];
    for (int t = threadIdx.x; t < 1024; t += blockDim.x) h[t] = 0u;
    __syncthreads();
    int img = blockIdx.y;
    const float4* o = (const float4*)(obj + (size_t)img * NA);
    int stride = gridDim.x * blockDim.x;
    int i = blockIdx.x * blockDim.x + threadIdx.x;
    for (; i + stride < NA / 4; i += 2 * stride) {
        float4 v0 = o[i];
        float4 v1 = o[i + stride];
        atomicAdd(&h[fkey(v0.x) >> 22], 1u);
        atomicAdd(&h[fkey(v0.y) >> 22], 1u);
        atomicAdd(&h[fkey(v0.z) >> 22], 1u);
        atomicAdd(&h[fkey(v0.w) >> 22], 1u);
        atomicAdd(&h[fkey(v1.x) >> 22], 1u);
        atomicAdd(&h[fkey(v1.y) >> 22], 1u);
        atomicAdd(&h[fkey(v1.z) >> 22], 1u);
        atomicAdd(&h[fkey(v1.w) >> 22], 1u);
    }
    if (i < NA / 4) {
        float4 v = o[i];
        atomicAdd(&h[fkey(v.x) >> 22], 1u);
        atomicAdd(&h[fkey(v.y) >> 22], 1u);
        atomicAdd(&h[fkey(v.z) >> 22], 1u);
        atomicAdd(&h[fkey(v.w) >> 22], 1u);
    }
    __syncthreads();
    for (int t = threadIdx.x; t < 1024; t += blockDim.x)
        if (h[t]) atomicAdd(&g_hist_c[img * 1024 + t], h[t]);
}

// ---------------- K2: pick coarse boundary bucket (1 warp/image) ------------
__global__ void k_select_c() {
    int img = blockIdx.x, lane = threadIdx.x;
    const unsigned* H = g_hist_c + img * 1024;
    unsigned part = 0;
    for (int r = lane * 32; r < lane * 32 + 32; r++) part += H[1023 - r];
    unsigned inc = part;
    for (int off = 1; off < 32; off <<= 1) {
        unsigned v = __shfl_up_sync(0xffffffffu, inc, off);
        if (lane >= off) inc += v;
    }
    unsigned needed = (unsigned)PRE_NMS;
    unsigned excl = inc - part;
    if (inc >= needed && excl < needed) {
        unsigned acc = excl;
        for (int r = lane * 32; r < lane * 32 + 32; r++) {
            unsigned hv = H[1023 - r];
            if (acc + hv >= needed) {
                g_bucket_c[img] = (unsigned)(1023 - r);
                g_above_c[img]  = acc;
                break;
            }
            acc += hv;
        }
    }
}

// ---------------- K3: fine histogram + collect (block-staged) ---------------
__global__ void k_hist_f(const float* __restrict__ obj) {
    __shared__ unsigned h[1024];
    __shared__ u64 su[SBUF], sb[SBUF];
    __shared__ int scu, scb, gu, gb;
    for (int t = threadIdx.x; t < 1024; t += blockDim.x) h[t] = 0u;
    if (threadIdx.x == 0) { scu = 0; scb = 0; }
    __syncthreads();
    int img = blockIdx.y;
    unsigned c = g_bucket_c[img];
    const float4* o = (const float4*)(obj + (size_t)img * NA);
    int stride = gridDim.x * blockDim.x;
    for (int i = blockIdx.x * blockDim.x + threadIdx.x; i < NA / 4; i += stride) {
        float4 v = o[i];
        unsigned k0 = fkey(v.x), k1 = fkey(v.y), k2 = fkey(v.z), k3 = fkey(v.w);
        unsigned mx = max(max(k0, k1), max(k2, k3));
        if ((mx >> 22) < c) continue;          // fast path: ~92% of iterations
#pragma unroll
        for (int j = 0; j < 4; j++) {
            unsigned key = (j == 0) ? k0 : (j == 1) ? k1 : (j == 2) ? k2 : k3;
            unsigned cb = key >> 22;
            if (cb < c) continue;
            u64 e = ((u64)key << 32) | (unsigned)(~(unsigned)(4 * i + j));
            if (cb > c) {
                int p = atomicAdd(&scu, 1);
                if (p < SBUF) su[p] = e;
                else {
                    int q = atomicAdd(&g_cand_cnt[img], 1);
                    if (q < CAND_CAP) g_cand[img * CAND_CAP + q] = e;
                }
            } else {
                atomicAdd(&h[(key >> 12) & 1023u], 1u);
                int p = atomicAdd(&scb, 1);
                if (p < SBUF) sb[p] = e;
                else {
                    int q = atomicAdd(&g_bcnt[img], 1);
                    if (q < BC_CAP) g_bcand[img * BC_CAP + q] = e;
                }
            }
        }
    }
    __syncthreads();
    if (threadIdx.x == 0) {
        int a = scu < SBUF ? scu : SBUF;
        gu = atomicAdd(&g_cand_cnt[img], a);
        int b2 = scb < SBUF ? scb : SBUF;
        gb = atomicAdd(&g_bcnt[img], b2);
    }
    __syncthreads();
    int nu = scu < SBUF ? scu : SBUF;
    for (int p = threadIdx.x; p < nu; p += blockDim.x) {
        int q = gu + p;
        if (q < CAND_CAP) g_cand[img * CAND_CAP + q] = su[p];
    }
    int nb = scb < SBUF ? scb : SBUF;
    for (int p = threadIdx.x; p < nb; p += blockDim.x) {
        int q = gb + p;
        if (q < BC_CAP) g_bcand[img * BC_CAP + q] = sb[p];
    }
    for (int t = threadIdx.x; t < 1024; t += blockDim.x)
        if (h[t]) atomicAdd(&g_hist_f[img * 1024 + t], h[t]);
}

// ---------------- K4: fine select + boundary filter (fused) -----------------
__global__ void k_select_f_compact() {
    int img = blockIdx.x;
    int lane = threadIdx.x & 31;
    __shared__ unsigned sT;
    if (threadIdx.x < 32) {               // warp 0: pick fine bucket
        const unsigned* H = g_hist_f + img * 1024;
        unsigned part = 0;
        for (int r = lane * 32; r < lane * 32 + 32; r++) part += H[1023 - r];
        unsigned inc = part;
        for (int off = 1; off < 32; off <<= 1) {
            unsigned v = __shfl_up_sync(0xffffffffu, inc, off);
            if (lane >= off) inc += v;
        }
        unsigned base   = g_above_c[img];
        unsigned needed = (unsigned)PRE_NMS - base;
        unsigned excl = inc - part;
        if (inc >= needed && excl < needed) {
            unsigned acc = excl;
            for (int r = lane * 32; r < lane * 32 + 32; r++) {
                unsigned hv = H[1023 - r];
                if (acc + hv >= needed) {
                    sT = (g_bucket_c[img] << 10) | (unsigned)(1023 - r);
                    break;
                }
                acc += hv;
            }
        }
    }
    __syncthreads();
    unsigned T = sT;
    int cnt = g_bcnt[img]; if (cnt > BC_CAP) cnt = BC_CAP;
    int nIter = (cnt + blockDim.x - 1) / blockDim.x;
    for (int it = 0; it < nIter; it++) {
        int i = it * blockDim.x + threadIdx.x;
        bool take = false;
        u64 e = 0ull;
        if (i < cnt) {
            e = g_bcand[img * BC_CAP + i];
            take = ((unsigned)(e >> 44) >= T);
        }
        unsigned m = __ballot_sync(0xffffffffu, take);
        if (m) {
            int ldr = __ffs(m) - 1;
            int base = 0;
            if (lane == ldr) base = atomicAdd(&g_cand_cnt[img], __popc(m));
            base = __shfl_sync(0xffffffffu, base, ldr);
            if (take) {
                int p = base + __popc(m & ((1u << lane) - 1u));
                if (p < CAND_CAP) g_cand[img * CAND_CAP + p] = e;
            }
        }
    }
}

// ---------------- K5: bitonic sort + decode + clip + sigmoid (fused) --------
__global__ void __launch_bounds__(1024, 1)
k_sortdecode(const float* __restrict__ deltas,
             const float* __restrict__ anchors) {
    extern __shared__ u64 s[];
    int img = blockIdx.x;
    int cnt = g_cand_cnt[img];
    if (cnt > CAND_CAP) cnt = CAND_CAP;
    unsigned S = (cnt <= 4096) ? 4096u : (unsigned)CAND_CAP;
    for (unsigned t = threadIdx.x; t < S; t += blockDim.x)
        s[t] = (t < (unsigned)cnt) ? g_cand[img * CAND_CAP + t] : 0ull;
    __syncthreads();
    for (unsigned k = 2; k <= S; k <<= 1) {
        for (unsigned j = k >> 1; j > 0; j >>= 1) {
            for (unsigned idx = threadIdx.x; idx < S; idx += blockDim.x) {
                unsigned ixj = idx ^ j;
                if (ixj > idx) {
                    u64 a = s[idx], b = s[ixj];
                    bool blk = ((idx & k) == 0u);     // descending overall
                    if (blk ? (a < b) : (a > b)) { s[idx] = b; s[ixj] = a; }
                }
            }
            __syncthreads();
        }
    }
    // decode top-4000 directly from sorted smem
    for (int t = threadIdx.x; t < 4096; t += blockDim.x) {
        bool inr = (t < PRE_NMS);
        u64 key = inr ? s[t] : 0ull;
        int idx = inr ? (int)(~(unsigned)key) : 0;
        float4 a = ((const float4*)anchors)[idx];
        float4 d = ((const float4*)deltas)[(size_t)img * NA + idx];
        float w = a.z - a.x, h = a.w - a.y;
        float cx = a.x + 0.5f * w, cy = a.y + 0.5f * h;
        float dw = fminf(d.z, BBOX_CLIP), dh = fminf(d.w, BBOX_CLIP);
        float pcx = d.x * w + cx, pcy = d.y * h + cy;
        float pw = expf(dw) * w, ph = expf(dh) * h;
        float x1 = pcx - 0.5f * pw, y1 = pcy - 0.5f * ph;
        float x2 = pcx + 0.5f * pw, y2 = pcy + 0.5f * ph;
        x1 = fminf(fmaxf(x1, 0.f), IMG_WF);
        y1 = fminf(fmaxf(y1, 0.f), IMG_HF);
        x2 = fminf(fmaxf(x2, 0.f), IMG_WF);
        y2 = fminf(fmaxf(y2, 0.f), IMG_HF);
        bool validb = false;
        if (inr) {
            g_box[img * PRE_NMS + t] = make_float4(x1, y1, x2, y2);
            validb = ((x2 - x1) >= MIN_SIZE) && ((y2 - y1) >= MIN_SIZE);
            float sc = unkey((unsigned)(key >> 32));
            g_prob[img * PRE_NMS + t] = 1.f / (1.f + expf(-sc));
        }
        unsigned bb = __ballot_sync(0xffffffffu, validb);
        if ((threadIdx.x & 31) == 0 && inr)
            g_vmask32[img * 128 + (t >> 5)] = bb;
    }
}

// ---------------- K6: IoU suppression bitmask (FMA compares) ----------------
__global__ void k_iou() {
    int img = blockIdx.z, rb = blockIdx.y, cb = blockIdx.x;
    if (cb * 64 + 64 <= rb * 128) return;  // entire col-block below diagonal
    __shared__ float4 cbox[64];
    __shared__ float  car[64];
    int col0 = cb * 64;
    if (threadIdx.x < 64) {
        int c = col0 + threadIdx.x;
        float4 q = (c < PRE_NMS) ? g_box[img * PRE_NMS + c] : make_float4(0, 0, 0, 0);
        cbox[threadIdx.x] = q;
        car[threadIdx.x] = (q.z - q.x) * (q.w - q.y);
    }
    __syncthreads();
    int row = rb * 128 + threadIdx.x;
    if (row >= PRE_NMS) return;
    if (col0 + 63 <= row) return;          // this row's word all below/equal diag
    float4 r = g_box[img * PRE_NMS + row];
    float ra = (r.z - r.x) * (r.w - r.y);
    unsigned mlo = 0u, mhi = 0u, blo = 0u, bhi = 0u;
#pragma unroll 16
    for (int j = 0; j < 64; j++) {
        float4 b = cbox[j];
        float xx1 = fmaxf(r.x, b.x), yy1 = fmaxf(r.y, b.y);
        float xx2 = fminf(r.z, b.z), yy2 = fminf(r.w, b.w);
        float ww = fmaxf(xx2 - xx1, 0.f), hh = fmaxf(yy2 - yy1, 0.f);
        float inter = ww * hh;
        float uni = (ra + car[j]) - inter;
        bool sup  = __fmaf_rn(-0.700007f, uni, inter) > 0.f;
        bool band = __fmaf_rn(-0.699993f, uni, inter) >= 0.f;
        unsigned bit = 1u << (j & 31);
        if (j < 32) { mlo |= sup ? bit : 0u; blo |= band ? bit : 0u; }
        else        { mhi |= sup ? bit : 0u; bhi |= band ? bit : 0u; }
    }
    u64 msup  = ((u64)mhi << 32) | mlo;
    u64 mband = (((u64)bhi << 32) | blo) & ~msup;
    int rel = row - col0;                  // keep only cols strictly above diag
    if (rel >= 0) {
        u64 hi = (rel >= 63) ? 0ull : (~0ull << (rel + 1));
        msup &= hi;
        mband &= hi;
    }
    while (mband) {                        // rare: bit-exact reference decision
        int j = __ffsll((long long)mband) - 1;
        mband &= mband - 1;
        float4 b = cbox[j];
        float xx1 = fmaxf(r.x, b.x), yy1 = fmaxf(r.y, b.y);
        float xx2 = fminf(r.z, b.z), yy2 = fminf(r.w, b.w);
        float ww = fmaxf(xx2 - xx1, 0.f), hh = fmaxf(yy2 - yy1, 0.f);
        float inter = ww * hh;
        float uni = (ra + car[j]) - inter;
        if ((inter / fmaxf(uni, 1e-9f)) > 0.7f) msup |= (1ull << j);
    }
    g_mask[((size_t)img * PRE_NMS + row) * WPR + cb] = msup;
}

// ---------------- K7: greedy NMS (2-bit speculative) + output (fused) -------
// 256 threads: keeps warp-0's fat register state under the per-block budget.
// layout: [proposals (8,1000,4) f32][scores (8,1000) f32]
__global__ void __launch_bounds__(256)
k_nmsout(float* __restrict__ out) {
    int img = blockIdx.x;
    __shared__ u64 diag_sh[64];
    __shared__ u64 s_km[63];
    __shared__ int s_kept[POST_NMS];
    __shared__ int s_n;
    __shared__ unsigned sh[256];
    int tid = threadIdx.x;

    if (tid < 32) {                        // warp 0: sequential greedy scan
        int lane = tid;
        const unsigned* vm = g_vmask32 + img * 128;
        u64 r0 = ~((u64)vm[2 * lane] | ((u64)vm[2 * lane + 1] << 32));
        u64 r1 = ~((u64)vm[64 + 2 * lane] | ((u64)vm[65 + 2 * lane] << 32));
        const u64* M = g_mask + (size_t)img * PRE_NMS * WPR;
        u64 nd0 = M[(size_t)(2 * lane) * WPR + 0];
        u64 nd1 = M[(size_t)(2 * lane + 1) * WPR + 0];
        int n = 0;
        for (int ch = 0; ch < 63; ch++) {
            diag_sh[2 * lane] = nd0;
            diag_sh[2 * lane + 1] = nd1;
            __syncwarp();
            if (ch < 62) {
                int base = (ch + 1) * 64;
                int ra2 = base + 2 * lane, rb2 = ra2 + 1;
                nd0 = (ra2 < PRE_NMS) ? M[(size_t)ra2 * WPR + (ch + 1)] : 0ull;
                nd1 = (rb2 < PRE_NMS) ? M[(size_t)rb2 * WPR + (ch + 1)] : 0ull;
            }
            u64 remw = (ch < 32) ? __shfl_sync(0xffffffffu, r0, ch)
                                 : __shfl_sync(0xffffffffu, r1, ch - 32);
            u64 km = 0ull;
#pragma unroll
            for (int b = 0; b < 64; b += 2) {
                u64 d0 = diag_sh[b], d1 = diag_sh[b + 1];
                u64 d01 = d0 | d1;                 // off-chain
                u64 c01 = remw | d1;
                u64 c10 = remw | d0;
                u64 c11 = remw | d01;
                bool k0  = (remw & (1ull << b)) == 0ull;
                bool k1k = (c10  & (1ull << (b + 1))) == 0ull;
                bool k1s = (remw & (1ull << (b + 1))) == 0ull;
                u64 lo  = k0 ? c10 : remw;
                u64 hi2 = k0 ? c11 : c01;
                bool k1 = k0 ? k1k : k1s;
                remw = k1 ? hi2 : lo;
                km |= (k0 ? (1ull << b) : 0ull) | (k1 ? (1ull << (b + 1)) : 0ull);
            }
            // parallel kept-list extraction (rank by popcount)
            {
                bool kb0 = (km >> lane) & 1ull;
                int rk0 = __popcll(km & ((1ull << lane) - 1ull));
                int slot0 = n + rk0;
                if (kb0 && slot0 < POST_NMS) s_kept[slot0] = ch * 64 + lane;
                int l2 = lane + 32;
                bool kb1 = (km >> l2) & 1ull;
                int rk1 = __popcll(km & ((1ull << l2) - 1ull));
                int slot1 = n + rk1;
                if (kb1 && slot1 < POST_NMS) s_kept[slot1] = ch * 64 + l2;
            }
            if (lane == 0) s_km[ch] = km;
            n += __popcll(km);
            if (n >= POST_NMS) break;
            // OR kept rows' full masks into remv, 8-wide batches for MLP
            u64 t = km;
            while (t) {
                int rr[8];
#pragma unroll
                for (int u = 0; u < 8; u++) {
                    if (t) { rr[u] = ch * 64 + (__ffsll((long long)t) - 1); t &= t - 1; }
                    else    rr[u] = -1;
                }
                u64 pa[8], pb[8];
#pragma unroll
                for (int u = 0; u < 8; u++) {
                    if (rr[u] >= 0) {
                        const u64* rp = M + (size_t)rr[u] * WPR;
                        pa[u] = rp[lane];
                        pb[u] = rp[32 + lane];   // word 63 never written -> 0
                    } else { pa[u] = 0ull; pb[u] = 0ull; }
                }
#pragma unroll
                for (int u = 0; u < 8; u++) { r0 |= pa[u]; r1 |= pb[u]; }
            }
            __syncwarp();
        }
        if (lane == 0) s_n = n;
    }
    __syncthreads();

    // ---- output assembly (256 threads) ----
    int n = s_n;
    int lim = n < POST_NMS ? n : POST_NMS;
    for (int s2 = tid; s2 < lim; s2 += 256) {
        int i = s_kept[s2];
        ((float4*)out)[img * POST_NMS + s2] = g_box[img * PRE_NMS + i];
        out[NB * POST_NMS * 4 + img * POST_NMS + s2] = g_prob[img * PRE_NMS + i];
    }
    if (n >= POST_NMS) return;
    // fill with non-kept indices ascending, score = -inf (top_k tie rule)
    unsigned base = 0;
    for (int chunk = 0; chunk < PRE_NMS; chunk += 256) {
        int i = chunk + tid;
        unsigned f = 0u;
        if (i < PRE_NMS) {
            u64 kw = s_km[i >> 6];
            f = ((kw >> (i & 63)) & 1ull) ? 0u : 1u;
        }
        sh[tid] = f;
        __syncthreads();
        for (int off = 1; off < 256; off <<= 1) {
            unsigned vv = (tid >= off) ? sh[tid - off] : 0u;
            __syncthreads();
            sh[tid] += vv;
            __syncthreads();
        }
        unsigned excl = sh[tid] - f;
        int slot = n + (int)(base + excl);
        if (f && slot < POST_NMS) {
            ((float4*)out)[img * POST_NMS + slot] = g_box[img * PRE_NMS + i];
            out[NB * POST_NMS * 4 + img * POST_NMS + slot] =
                __int_as_float(0xff800000);  // -inf
        }
        base += sh[255];
        __syncthreads();
    }
}

// ---------------- host ------------------------------------------------------
extern "C" void kernel_launch(void* const* d_in, const int* in_sizes, int n_in,
                              void* d_out, int out_size) {
    const float* obj     = (const float*)d_in[0];   // (8, 750000)
    const float* deltas  = (const float*)d_in[1];   // (8, 750000, 4)
    const float* anchors = (const float*)d_in[2];   // (750000, 4)
    float* out = (float*)d_out;

    k_zero<<<8, 1024>>>();
    k_hist_c<<<dim3(144, NB), 256>>>(obj);
    k_select_c<<<NB, 32>>>();
    k_hist_f<<<dim3(144, NB), 256>>>(obj);
    k_select_f_compact<<<NB, 256>>>();

    cudaFuncSetAttribute(k_sortdecode, cudaFuncAttributeMaxDynamicSharedMemorySize,
                         CAND_CAP * (int)sizeof(u64));
    k_sortdecode<<<NB, 1024, CAND_CAP * sizeof(u64)>>>(deltas, anchors);

    k_iou<<<dim3(63, 32, NB), 128>>>();
    k_nmsout<<<NB, 256>>>(out);
}